// round 4
// baseline (speedup 1.0000x reference)
#include <cuda_runtime.h>
#include <cuda_bf16.h>
#include <math_constants.h>

// GeomAttention: B=2, L=S=2048, H=8, E=D=32, fp32.
// scores = (0.5*dot - 0.5*relu(qn2*kn2 - dot^2))/sqrt(E); softmax; out = attn @ V.
//
// R4: lane-pair E-split (each thread owns 16 of 32 elements for 2 query rows;
// shfl_xor(1) combines dot partials). Halves per-thread registers -> 12 warps/SM
// (was ~7), doubles warp-level parallelism at identical FFMA2 work. Fused
// split-S(2) + last-block merge retained from R3.

static constexpr int B_ = 2, L_ = 2048, H_ = 8, E_ = 32;
static constexpr int SPLITS = 2;
static constexpr int SKEYS  = L_ / SPLITS;   // 1024
static constexpr int TS = 64;                // keys per SMEM tile
static constexpr int CH = 8;                 // keys per score chunk
static constexpr int THREADS = 64;           // 2 warps
static constexpr int PAIRS = THREADS / 2;    // 32 lane pairs -> 64 rows per block
static constexpr int ROWSPB = 2 * PAIRS;     // 64 query rows per block
static constexpr int NR = B_ * L_ * H_;      // 32768 rows
static constexpr int NGROUPS = (L_ / ROWSPB) * H_ * B_;  // 512

__device__ float  g_m[SPLITS * NR];
__device__ float  g_l[SPLITS * NR];
__device__ float4 g_acc[SPLITS * NR * 8];
__device__ int    g_cnt[NGROUPS];            // zero-init; self-resetting

typedef unsigned long long u64;

__device__ __forceinline__ u64 pk2(float a, float b) {
    u64 r; asm("mov.b64 %0, {%1,%2};" : "=l"(r) : "f"(a), "f"(b)); return r;
}
__device__ __forceinline__ float2 upk2(u64 v) {
    float2 r; asm("mov.b64 {%0,%1}, %2;" : "=f"(r.x), "=f"(r.y) : "l"(v)); return r;
}
__device__ __forceinline__ u64 ffma2(u64 a, u64 b, u64 c) {
    u64 d; asm("fma.rn.f32x2 %0, %1, %2, %3;" : "=l"(d) : "l"(a), "l"(b), "l"(c)); return d;
}
__device__ __forceinline__ u64 fmul2_(u64 a, u64 b) {
    u64 d; asm("mul.rn.f32x2 %0, %1, %2;" : "=l"(d) : "l"(a), "l"(b)); return d;
}

__global__ __launch_bounds__(THREADS, 6) void geom_attn_fused(
    const float* __restrict__ Q, const float* __restrict__ K,
    const float* __restrict__ V, float* __restrict__ O)
{
    __shared__ float4 sK[TS * 8];
    __shared__ float4 sV[TS * 8];
    __shared__ float  sKn2[TS];
    __shared__ int    sLast;

    const int tid   = threadIdx.x;
    const int pr    = tid >> 1;          // lane pair id within block (0..31)
    const int half  = tid & 1;           // which 16 elements this lane owns
    const int h     = blockIdx.y;
    const int bz    = blockIdx.z;
    const int b     = bz >> 1;           // SPLITS == 2
    const int split = bz & 1;
    const int lbase = blockIdx.x * ROWSPB;
    const int l0    = lbase + pr;
    const int l1    = l0 + PAIRS;

    // ---- load this lane's 16-element slices of both query rows ----
    const float4* qp0 = (const float4*)(Q + (((size_t)b * L_ + l0) * H_ + h) * E_) + half * 4;
    const float4* qp1 = (const float4*)(Q + (((size_t)b * L_ + l1) * H_ + h) * E_) + half * 4;
    u64 qa[8], qb[8];
    float qn2a = 0.f, qn2b = 0.f;
    #pragma unroll
    for (int j = 0; j < 4; j++) {
        float4 t = qp0[j];
        qa[2*j] = pk2(t.x, t.y); qa[2*j+1] = pk2(t.z, t.w);
        qn2a += t.x*t.x + t.y*t.y + t.z*t.z + t.w*t.w;
        float4 u = qp1[j];
        qb[2*j] = pk2(u.x, u.y); qb[2*j+1] = pk2(u.z, u.w);
        qn2b += u.x*u.x + u.y*u.y + u.z*u.z + u.w*u.w;
    }
    qn2a += __shfl_xor_sync(0xffffffffu, qn2a, 1);
    qn2b += __shfl_xor_sync(0xffffffffu, qn2b, 1);

    float m0 = -CUDART_INF_F, m1 = -CUDART_INF_F, ls0 = 0.f, ls1 = 0.f;
    u64 acca[8], accb[8];
    #pragma unroll
    for (int j = 0; j < 8; j++) { acca[j] = 0ull; accb[j] = 0ull; }

    const float scale = 0.5f * rsqrtf((float)E_);
    const int key0 = split * SKEYS;
    const float* kbase = K + (((size_t)b * L_) * H_ + h) * E_;
    const float* vbase = V + (((size_t)b * L_) * H_ + h) * E_;

    for (int s0 = 0; s0 < SKEYS; s0 += TS) {
        #pragma unroll
        for (int i = tid; i < TS * 8; i += THREADS) {
            int r = i >> 3, j = i & 7;
            size_t off = (size_t)(key0 + s0 + r) * (H_ * E_);
            sK[i] = ((const float4*)(kbase + off))[j];
            sV[i] = ((const float4*)(vbase + off))[j];
        }
        __syncthreads();
        {   // per-key |k|^2 (one key per thread, THREADS == TS); rotate j vs banks
            float kn = 0.f;
            #pragma unroll
            for (int jj = 0; jj < 8; jj++) {
                int j = (jj + tid) & 7;
                float4 kk = sK[tid * 8 + j];
                kn += kk.x*kk.x + kk.y*kk.y + kk.z*kk.z + kk.w*kk.w;
            }
            sKn2[tid] = kn;
        }
        __syncthreads();

        for (int c0 = 0; c0 < TS; c0 += CH) {
            float sa[CH], sb[CH];
            // ---- phase 1: partial dots on this lane's 16 elems, pair-combine ----
            #pragma unroll
            for (int u = 0; u < CH; u++) {
                const ulonglong2* kp = (const ulonglong2*)&sK[(c0 + u) * 8] + half * 4;
                u64 a0 = 0ull, a1 = 0ull, b0 = 0ull, b1 = 0ull;
                #pragma unroll
                for (int j = 0; j < 4; j++) {
                    ulonglong2 kk = kp[j];
                    a0 = ffma2(qa[2*j],   kk.x, a0);
                    a1 = ffma2(qa[2*j+1], kk.y, a1);
                    b0 = ffma2(qb[2*j],   kk.x, b0);
                    b1 = ffma2(qb[2*j+1], kk.y, b1);
                }
                float2 ra0 = upk2(a0), ra1 = upk2(a1);
                float2 rb0 = upk2(b0), rb1 = upk2(b1);
                float pda = (ra0.x + ra0.y) + (ra1.x + ra1.y);
                float pdb = (rb0.x + rb0.y) + (rb1.x + rb1.y);
                float dota = pda + __shfl_xor_sync(0xffffffffu, pda, 1);
                float dotb = pdb + __shfl_xor_sync(0xffffffffu, pdb, 1);
                float kn2  = sKn2[c0 + u];
                float wa = fmaxf(fmaf(qn2a, kn2, -dota * dota), 0.f);
                float wb = fmaxf(fmaf(qn2b, kn2, -dotb * dotb), 0.f);
                sa[u] = scale * (dota - wa);
                sb[u] = scale * (dotb - wb);
            }
            // ---- chunk max + single lazy rescale (uniform within a pair) ----
            float cma = sa[0], cmb = sb[0];
            #pragma unroll
            for (int u = 1; u < CH; u++) { cma = fmaxf(cma, sa[u]); cmb = fmaxf(cmb, sb[u]); }
            if (cma > m0 || cmb > m1) {
                float mna = fmaxf(m0, cma), mnb = fmaxf(m1, cmb);
                float ca = __expf(m0 - mna), cb = __expf(m1 - mnb);
                ls0 *= ca; ls1 *= cb;
                u64 cca = pk2(ca, ca), ccb = pk2(cb, cb);
                #pragma unroll
                for (int j = 0; j < 8; j++) {
                    acca[j] = fmul2_(acca[j], cca);
                    accb[j] = fmul2_(accb[j], ccb);
                }
                m0 = mna; m1 = mnb;
            }
            // ---- phase 2: exp + PV accumulate on this lane's 16 elems ----
            #pragma unroll
            for (int u = 0; u < CH; u++) {
                float pa = __expf(sa[u] - m0);
                float pb = __expf(sb[u] - m1);
                ls0 += pa; ls1 += pb;
                u64 ppa = pk2(pa, pa), ppb = pk2(pb, pb);
                const ulonglong2* vp = (const ulonglong2*)&sV[(c0 + u) * 8] + half * 4;
                #pragma unroll
                for (int j = 0; j < 4; j++) {
                    ulonglong2 vv = vp[j];
                    acca[2*j]   = ffma2(ppa, vv.x, acca[2*j]);
                    acca[2*j+1] = ffma2(ppa, vv.y, acca[2*j+1]);
                    accb[2*j]   = ffma2(ppb, vv.x, accb[2*j]);
                    accb[2*j+1] = ffma2(ppb, vv.y, accb[2*j+1]);
                }
            }
        }
        __syncthreads();
    }

    // ---- write partials (each lane writes its 4 float4 chunks per row) ----
    const int r0 = ((b * L_ + l0) * H_ + h);
    const int r1 = ((b * L_ + l1) * H_ + h);
    if (half == 0) {   // ls/m identical across the pair
        g_m[split * NR + r0] = m0; g_l[split * NR + r0] = ls0;
        g_m[split * NR + r1] = m1; g_l[split * NR + r1] = ls1;
    }
    float4* pa4 = &g_acc[(size_t)(split * NR + r0) * 8 + half * 4];
    float4* pb4 = &g_acc[(size_t)(split * NR + r1) * 8 + half * 4];
    #pragma unroll
    for (int j = 0; j < 4; j++) {
        float2 x = upk2(acca[2*j]), y = upk2(acca[2*j+1]);
        pa4[j] = make_float4(x.x, x.y, y.x, y.y);
        float2 u = upk2(accb[2*j]), v = upk2(accb[2*j+1]);
        pb4[j] = make_float4(u.x, u.y, v.x, v.y);
    }

    // ---- last block of this (b,h,lgroup) merges the two splits ----
    const int g = blockIdx.x + (L_ / ROWSPB) * (h + H_ * b);
    __threadfence();
    if (tid == 0) {
        int prev = atomicAdd(&g_cnt[g], 1);
        sLast = (prev == SPLITS - 1);
    }
    __syncthreads();
    if (!sLast) return;
    __threadfence();

    // 64 threads merge 64 rows x 8 float4 chunks = 512 items.
    #pragma unroll 1
    for (int it = 0; it < (ROWSPB * 8) / THREADS; it++) {
        int item = it * THREADS + tid;
        int rl = item >> 3;
        int jj = item & 7;
        int r  = ((b * L_ + lbase + rl) * H_ + h);
        float mA = g_m[r], mB = g_m[NR + r];
        float mm = fmaxf(mA, mB);
        float w0 = __expf(mA - mm), w1 = __expf(mB - mm);
        float denom = w0 * g_l[r] + w1 * g_l[NR + r];
        float inv = 1.0f / denom;
        float4 a0 = g_acc[(size_t)r * 8 + jj];
        float4 a1 = g_acc[(size_t)(NR + r) * 8 + jj];
        float4 o;
        o.x = (w0 * a0.x + w1 * a1.x) * inv;
        o.y = (w0 * a0.y + w1 * a1.y) * inv;
        o.z = (w0 * a0.z + w1 * a1.z) * inv;
        o.w = (w0 * a0.w + w1 * a1.w) * inv;
        ((float4*)O)[(size_t)r * 8 + jj] = o;
    }
    if (tid == 0) g_cnt[g] = 0;   // self-reset for next graph replay
}

extern "C" void kernel_launch(void* const* d_in, const int* in_sizes, int n_in,
                              void* d_out, int out_size) {
    const float* Q = (const float*)d_in[0];
    const float* K = (const float*)d_in[1];
    const float* V = (const float*)d_in[2];
    float* O = (float*)d_out;
    (void)in_sizes; (void)n_in; (void)out_size;
    dim3 grid(L_ / ROWSPB, H_, B_ * SPLITS);   // 32 x 8 x 4 = 1024 blocks
    geom_attn_fused<<<grid, THREADS>>>(Q, K, V, O);
}